// round 7
// baseline (speedup 1.0000x reference)
#include <cuda_runtime.h>
#include <cstdint>

#define NUM_C   64
#define FD      128
#define FD4     32          // float4 per feature row
#define BLK     256
#define NWARP   8
#define GRID    592         // 4 blocks per SM (148 SMs)
#define PER_CAP 1792        // max rows per block (ceil(1e6/592)=1690)
#define DEPTH   8           // cp.async ring slots per warp
#define N_PAIRS 2016        // 64*63/2

__device__ float        g_sums[NUM_C * FD];
__device__ int          g_counts[NUM_C];
__device__ float        g_sumsq;
__device__ unsigned int g_ticket;

__device__ __forceinline__ void cp16(uint32_t dst_smem, const void* src) {
    asm volatile("cp.async.cg.shared.global [%0], [%1], 16;\n"
                 :: "r"(dst_smem), "l"(src) : "memory");
}
#define CP_COMMIT()   asm volatile("cp.async.commit_group;\n" ::: "memory")
#define CP_WAIT7()    asm volatile("cp.async.wait_group 7;\n" ::: "memory")
#define CP_WAITALL()  asm volatile("cp.async.wait_all;\n" ::: "memory")

__device__ __forceinline__ void flush_acc(int c, int l, const float4& a) {
    float* gs = &g_sums[c * FD + (l << 2)];
    atomicAdd(gs + 0, a.x); atomicAdd(gs + 1, a.y);
    atomicAdd(gs + 2, a.z); atomicAdd(gs + 3, a.w);
}

__global__ void __launch_bounds__(BLK, 4)
fused_k(const float* __restrict__ feat, const int* __restrict__ tgt, int B,
        float* __restrict__ out)
{
    // 32KB: cp.async staging ring during phase C; aliased as `cent` in epilogue
    __shared__ float4 stage[NWARP * DEPTH * 32];
    __shared__ unsigned int  scomb[PER_CAP];     // sorted: rowid | (class<<16)
    __shared__ unsigned char stgt[PER_CAP];
    __shared__ int   hist[NUM_C];
    __shared__ int   cur[NUM_C];
    __shared__ float s_red[NWARP], s_sq[NWARP], s_hred[NWARP];
    __shared__ int   s_last;

    const int tid = threadIdx.x;
    const int w = tid >> 5, l = tid & 31;

    const int per = (B + GRID - 1) / GRID;
    const int r0  = blockIdx.x * per;
    int n = B - r0; if (n > per) n = per; if (n < 0) n = 0;

    if (tid < NUM_C) hist[tid] = 0;
    __syncthreads();

    // ---- phase A: load targets, histogram ----
    for (int i = tid; i < n; i += BLK) {
        int t = tgt[r0 + i];
        stgt[i] = (unsigned char)t;
        atomicAdd(&hist[t], 1);
    }
    __syncthreads();

    // ---- exclusive prefix over 64 counts (warp 0) ----
    if (w == 0) {
        int a = hist[l], b = hist[l + 32];
        int ia = a, ib = b;
#pragma unroll
        for (int o = 1; o < 32; o <<= 1) { int t = __shfl_up_sync(0xffffffffu, ia, o); if (l >= o) ia += t; }
#pragma unroll
        for (int o = 1; o < 32; o <<= 1) { int t = __shfl_up_sync(0xffffffffu, ib, o); if (l >= o) ib += t; }
        int totA = __shfl_sync(0xffffffffu, ia, 31);
        cur[l]      = ia - a;
        cur[l + 32] = totA + ib - b;
    }
    __syncthreads();

    // ---- phase B: scatter (rowid | class<<16) into class-sorted order ----
    for (int i = tid; i < n; i += BLK) {
        int t = stgt[i];
        int pos = atomicAdd(&cur[t], 1);
        scomb[pos] = (unsigned int)i | ((unsigned int)t << 16);
    }
    __syncthreads();

    // ---- phase C: cp.async-staged gather, register accumulate ----
    const float4* fbase = (const float4*)feat;
    const int p0 = (n * w) / NWARP;
    const int p1 = (n * (w + 1)) / NWARP;
    const int total = p1 - p0;

    // this lane's 16B target inside each of this warp's DEPTH slots
    const uint32_t sb = (uint32_t)__cvta_generic_to_shared(stage)
                      + (uint32_t)((w * DEPTH * 32 + l) * 16);

    // prologue: fill the ring (commit one group per slot, possibly empty)
#pragma unroll
    for (int k = 0; k < DEPTH; k++) {
        if (k < total) {
            unsigned int cb = scomb[p0 + k];
            cp16(sb + k * 512, fbase + (size_t)(r0 + (cb & 0xffffu)) * FD4 + l);
        }
        CP_COMMIT();
    }

    float sq0 = 0.f, sq1 = 0.f;
    float4 acc = make_float4(0.f, 0.f, 0.f, 0.f);
    int ccur = (total > 0) ? (int)(scomb[p0] >> 16) : 0;

    for (int t = 0; t < total; t++) {
        CP_WAIT7();                                   // oldest slot's row has landed
        const int slot = t & (DEPTH - 1);
        float4 x = stage[(w * DEPTH + slot) * 32 + l];
        int c = (int)(scomb[p0 + t] >> 16);

        const int tn = t + DEPTH;                     // refill this slot
        if (tn < total) {
            unsigned int cb2 = scomb[p0 + tn];
            cp16(sb + slot * 512, fbase + (size_t)(r0 + (cb2 & 0xffffu)) * FD4 + l);
        }
        CP_COMMIT();

        if (c != ccur) {                              // warp-uniform, rare
            flush_acc(ccur, l, acc);
            acc = make_float4(0.f, 0.f, 0.f, 0.f);
            ccur = c;
        }
        acc.x += x.x; acc.y += x.y; acc.z += x.z; acc.w += x.w;
        if (t & 1) sq1 = fmaf(x.x, x.x, fmaf(x.y, x.y, fmaf(x.z, x.z, fmaf(x.w, x.w, sq1))));
        else       sq0 = fmaf(x.x, x.x, fmaf(x.y, x.y, fmaf(x.z, x.z, fmaf(x.w, x.w, sq0))));
    }
    if (total > 0) flush_acc(ccur, l, acc);
    CP_WAITALL();                                     // drain before smem reuse

    // ---- block-level reductions & flush ----
    float sq = sq0 + sq1;
#pragma unroll
    for (int o = 16; o > 0; o >>= 1) sq += __shfl_down_sync(0xffffffffu, sq, o);
    if (l == 0) s_sq[w] = sq;
    if (tid < NUM_C) atomicAdd(&g_counts[tid], hist[tid]);
    __syncthreads();
    if (tid == 0) {
        float t = 0.f;
#pragma unroll
        for (int k = 0; k < NWARP; k++) t += s_sq[k];
        atomicAdd(&g_sumsq, t);
    }

    __threadfence();
    __syncthreads();
    if (tid == 0) {
        unsigned int tk = atomicAdd(&g_ticket, 1u);
        s_last = (tk == gridDim.x - 1);
    }
    __syncthreads();
    if (!s_last) return;

    // ================= last block: epilogue =================
    __threadfence();
    float* cent = (float*)stage;                      // alias staging ring (32KB)

    float ipart = 0.f;
    for (int i = tid; i < NUM_C * FD; i += BLK) {
        const int c = i >> 7;
        float cntc = fmaxf((float)g_counts[c], 1.0f);
        float s  = g_sums[i];
        float ce = s / cntc;
        cent[i]  = ce;
        ipart   += s * ce;                 // sum_c cnt_c * ||cent_c||^2
        g_sums[i] = 0.f;                   // reset for next graph replay
    }
    float ssq = 0.f;
    if (tid == 0) { ssq = g_sumsq; g_sumsq = 0.f; g_ticket = 0u; }
    __syncthreads();                       // all reads of g_counts done
    if (tid < NUM_C) g_counts[tid] = 0;

#pragma unroll
    for (int o = 16; o > 0; o >>= 1) ipart += __shfl_down_sync(0xffffffffu, ipart, o);
    if (l == 0) s_red[w] = ipart;
    __syncthreads();

    // pairwise hinge: one (i,j) pair per warp iter, lanes cover 128 dims as float4
    const float4* c4 = (const float4*)cent;
    float hsum = 0.f;
    for (int i = w; i < NUM_C - 1; i += NWARP) {
        float4 a = c4[i * FD4 + l];
        for (int j = i + 1; j < NUM_C; j++) {
            float4 b = c4[j * FD4 + l];
            float dx = a.x - b.x, dy = a.y - b.y, dz = a.z - b.z, dw = a.w - b.w;
            float d2 = dx * dx + dy * dy + dz * dz + dw * dw;
#pragma unroll
            for (int o = 16; o > 0; o >>= 1) d2 += __shfl_down_sync(0xffffffffu, d2, o);
            if (l == 0) {
                float wt = (i == 1 && j == 2) ? 2.0f : 1.0f;
                hsum += wt * fmaxf(2.0f - d2, 0.0f);     // MARGIN = 2
            }
        }
    }
    if (l == 0) s_hred[w] = hsum;
    __syncthreads();

    if (tid == 0) {
        float isum = 0.f, hs = 0.f;
#pragma unroll
        for (int k = 0; k < NWARP; k++) { isum += s_red[k]; hs += s_hred[k]; }
        out[0] = (ssq - isum) / (float)B + hs / (float)N_PAIRS;
    }
}

extern "C" void kernel_launch(void* const* d_in, const int* in_sizes, int n_in,
                              void* d_out, int out_size) {
    const float* feat = (const float*)d_in[0];
    const int*   tgt  = (const int*)d_in[1];
    const int B = in_sizes[1];
    fused_k<<<GRID, BLK>>>(feat, tgt, B, (float*)d_out);
}